// round 6
// baseline (speedup 1.0000x reference)
#include <cuda_runtime.h>
#include <cstdint>

typedef unsigned long long ull;

#define BB 512
#define TT 1024
#define IDIM 15
#define HH 64
#define ODIM 11
#define CHUNK 16
#define NCHUNK (TT/CHUNK)

// scratch (static __device__ — no allocations in kernel_launch)
__device__ __align__(16) float g_xpad[(size_t)BB*TT*16];   // x padded 15 -> 16

// ---- f32x2 helpers ----
__device__ __forceinline__ ull ffma2(ull a, ull b, ull c){
    ull d; asm("fma.rn.f32x2 %0, %1, %2, %3;" : "=l"(d) : "l"(a), "l"(b), "l"(c)); return d;
}
__device__ __forceinline__ ull fadd2(ull a, ull b){
    ull d; asm("add.rn.f32x2 %0, %1, %2;" : "=l"(d) : "l"(a), "l"(b)); return d;
}
__device__ __forceinline__ ull pack2(float x, float y){
    ull r; asm("mov.b64 %0, {%1, %2};" : "=l"(r) : "f"(x), "f"(y)); return r;
}
__device__ __forceinline__ float2 unpack2(ull v){
    float2 r; asm("mov.b64 {%0, %1}, %2;" : "=f"(r.x), "=f"(r.y) : "l"(v)); return r;
}

// ---- kernel 0: pad x [B,T,15] -> [B,T,16], float4 both directions via smem ----
__global__ void __launch_bounds__(256) pad_x_kernel(const float* __restrict__ x){
    __shared__ float xsm[256*IDIM];
    const int tid = threadIdx.x;
    const float4* src4 = (const float4*)(x + (size_t)blockIdx.x * (256*IDIM));
    #pragma unroll
    for (int k=0;k<4;k++){
        int idx = tid + k*256;
        if (idx < 960) ((float4*)xsm)[idx] = src4[idx];
    }
    __syncthreads();
    float4* dst4 = (float4*)(g_xpad + (size_t)blockIdx.x * (256*16));
    #pragma unroll
    for (int k=0;k<4;k++){
        int idx = tid + k*256;
        int row = idx >> 2, q = idx & 3;
        const float* rp = xsm + row*IDIM + q*4;
        float f0 = rp[0], f1 = rp[1], f2 = rp[2];
        float f3 = (q == 3) ? 0.f : rp[3];
        dst4[idx] = make_float4(f0, f1, f2, f3);
    }
}

// ---- kernel 1: fused xproj + recurrence + folded decoder. warp == one batch ----
__global__ void __launch_bounds__(128,1) rnn_dec_kernel(
    const float* __restrict__ W_ih, const float* __restrict__ b_ih,
    const float* __restrict__ W_hh, const float* __restrict__ b_hh,
    const float* __restrict__ W_dec, const float* __restrict__ b_dec,
    float* __restrict__ out, float* __restrict__ h_out)
{
    __shared__ __align__(16) float xs[2][4][CHUNK*16];   // 2 x 4 x 1KB = 8KB
    __shared__ __align__(16) ull  h_sh[4][2][32];        // per-warp double-buffered h

    const int wid = threadIdx.x >> 5;
    const int l   = threadIdx.x & 31;
    const int b   = blockIdx.x * 4 + wid;
    const int j0  = 2*l, j1 = j0 + 1;

    // W_hh rows j0,j1 in registers, k-paired as f32x2 (128 regs)
    ull w0[32], w1[32];
    {
        const ull* wp = (const ull*)W_hh;
        #pragma unroll
        for (int q=0;q<32;q++){ w0[q] = wp[j0*32+q]; w1[q] = wp[j1*32+q]; }
    }
    // W_ih rows j0,j1, i-paired (i=15 padded with 0)
    ull wi0[8], wi1[8];
    #pragma unroll
    for (int q=0;q<8;q++){
        float a0 = W_ih[j0*IDIM + 2*q];
        float a1 = (2*q+1 < IDIM) ? W_ih[j0*IDIM + 2*q + 1] : 0.f;
        wi0[q] = pack2(a0,a1);
        float c0 = W_ih[j1*IDIM + 2*q];
        float c1 = (2*q+1 < IDIM) ? W_ih[j1*IDIM + 2*q + 1] : 0.f;
        wi1[q] = pack2(c0,c1);
    }
    const ull bias0 = pack2(b_ih[j0]+b_hh[j0], 0.f);
    const ull bias1 = pack2(b_ih[j1]+b_hh[j1], 0.f);

    // decoder: lane l<22 -> output o=l>>1, K-half = l&1; wd covers that half (32 regs)
    const int o = l >> 1;
    const bool half0 = (l & 1) == 0;
    const bool dec_lane  = (l < 22);
    const bool dec_store = dec_lane && half0;
    ull wd[16];
    float bdec = 0.f;
    if (dec_lane){
        const ull* wdp = (const ull*)W_dec;
        const int hoff = half0 ? 0 : 16;
        #pragma unroll
        for (int q=0;q<16;q++) wd[q] = wdp[o*32 + hoff + q];
        bdec = b_dec[o];
    } else {
        #pragma unroll
        for (int q=0;q<16;q++) wd[q] = 0ULL;
    }
    const bool dlo = dec_lane && half0;     // dec over hv q=0..7
    const bool dhi = dec_lane && !half0;    // dec over hv q=8..15

    h_sh[wid][1][l] = 0ULL;   // h_{-1} = 0 (t=0 reads slot 1)

    const uint32_t xs_base = (uint32_t)__cvta_generic_to_shared(&xs[0][wid][0]);
    const float* xsrc = g_xpad + (size_t)b * (TT*16);

    auto prefetch = [&](int c){
        if (c < NCHUNK){
            const float* src = xsrc + (size_t)c * (CHUNK*16);
            uint32_t dst = xs_base + (uint32_t)(c & 1) * (uint32_t)sizeof(xs[0]);
            #pragma unroll
            for (int q=0;q<2;q++){
                int idx = q*32 + l;
                asm volatile("cp.async.ca.shared.global [%0], [%1], 16;\n"
                    :: "r"(dst + (uint32_t)(idx*16)), "l"(src + idx*4) : "memory");
            }
        }
        asm volatile("cp.async.commit_group;\n" ::: "memory");
    };

    prefetch(0);
    float* outp = out + (size_t)b * (TT*ODIM);

    for (int c=0; c<NCHUNK; c++){
        prefetch(c+1);
        asm volatile("cp.async.wait_group 1;\n" ::: "memory");
        __syncwarp();                                   // chunk boundary only
        const float* xpb = &xs[c & 1][wid][0];

        #pragma unroll 4
        for (int tt=0; tt<CHUNK; tt++){
            // parity is compile-time under even partial unroll
            const int rs = (tt & 1) ^ 1;   // slot holding h_{t-1}
            const int ws =  tt & 1;        // slot for h_t
            const int t  = c*CHUNK + tt;

            // xproj: 4 broadcast LDS.128 + 16 ffma2, independent of h
            const ulonglong2* xv = (const ulonglong2*)(xpb + tt*16);
            ull xa0 = bias0, xa1 = bias1;
            #pragma unroll
            for (int q=0;q<4;q++){
                ulonglong2 xq = xv[q];
                xa0 = ffma2(xq.x, wi0[2*q],   xa0);
                xa1 = ffma2(xq.x, wi1[2*q],   xa1);
                xa0 = ffma2(xq.y, wi0[2*q+1], xa0);
                xa1 = ffma2(xq.y, wi1[2*q+1], xa1);
            }

            // recurrence + folded decoder on the SAME hv broadcast stream
            const ulonglong2* hp = (const ulonglong2*)&h_sh[wid][rs][0];
            ull aa0=0ULL, aa1=0ULL, ab0=0ULL, ab1=0ULL;
            ull d0=0ULL, d1=0ULL;
            #pragma unroll
            for (int q=0;q<16;q++){
                ulonglong2 hv = hp[q];
                aa0 = ffma2(hv.x, w0[2*q],   aa0);
                aa1 = ffma2(hv.x, w1[2*q],   aa1);
                ab0 = ffma2(hv.y, w0[2*q+1], ab0);
                ab1 = ffma2(hv.y, w1[2*q+1], ab1);
                if (q < 8){
                    if (dlo){   // predicated FFMA2, wd index compile-time
                        d0 = ffma2(hv.x, wd[2*q],   d0);
                        d1 = ffma2(hv.y, wd[2*q+1], d1);
                    }
                } else {
                    if (dhi){
                        d0 = ffma2(hv.x, wd[2*(q-8)],   d0);
                        d1 = ffma2(hv.y, wd[2*(q-8)+1], d1);
                    }
                }
            }

            // decoder finalize (emits step t-1)
            float2 ds = unpack2(fadd2(d0,d1));
            float dp = ds.x + ds.y;
            float dq = __shfl_down_sync(0xffffffffu, dp, 1);

            // recurrence finalize
            float2 s0 = unpack2(fadd2(fadd2(aa0, ab0), xa0));
            float2 s1 = unpack2(fadd2(fadd2(aa1, ab1), xa1));
            float h0v = fmaxf(s0.x + s0.y, 0.f);
            float h1v = fmaxf(s1.x + s1.y, 0.f);
            h_sh[wid][ws][l] = pack2(h0v, h1v);

            if (t > 0 && dec_store){
                outp[(size_t)(t-1)*ODIM + o] = fmaxf(dp + dq + bdec, 0.f);
            }
            // converged warp: compiler-only ordering between STS and next LDS
            asm volatile("" ::: "memory");
        }
    }

    // final decoder for t = T-1 (h_{1023} is in slot 1) + final hidden state
    {
        __syncwarp();
        const ulonglong2* hp = (const ulonglong2*)&h_sh[wid][1][0];
        ull d0=0ULL, d1=0ULL;
        #pragma unroll
        for (int q=0;q<16;q++){
            ulonglong2 hv = hp[q];
            if (q < 8){
                if (dlo){
                    d0 = ffma2(hv.x, wd[2*q],   d0);
                    d1 = ffma2(hv.y, wd[2*q+1], d1);
                }
            } else {
                if (dhi){
                    d0 = ffma2(hv.x, wd[2*(q-8)],   d0);
                    d1 = ffma2(hv.y, wd[2*(q-8)+1], d1);
                }
            }
        }
        float2 ds = unpack2(fadd2(d0,d1));
        float dp = ds.x + ds.y;
        float dq = __shfl_down_sync(0xffffffffu, dp, 1);
        if (dec_store){
            outp[(size_t)(TT-1)*ODIM + o] = fmaxf(dp + dq + bdec, 0.f);
        }
        ((ull*)h_out)[b*32 + l] = h_sh[wid][1][l];
    }
}

extern "C" void kernel_launch(void* const* d_in, const int* in_sizes, int n_in,
                              void* d_out, int out_size)
{
    const float* x     = (const float*)d_in[0];
    const float* W_ih  = (const float*)d_in[1];
    const float* b_ih  = (const float*)d_in[2];
    const float* W_hh  = (const float*)d_in[3];
    const float* b_hh  = (const float*)d_in[4];
    const float* W_dec = (const float*)d_in[5];
    const float* b_dec = (const float*)d_in[6];
    float* out = (float*)d_out;

    (void)in_sizes; (void)n_in; (void)out_size;

    pad_x_kernel<<<(BB*TT)/256, 256>>>(x);
    rnn_dec_kernel<<<BB/4, 128>>>(W_ih, b_ih, W_hh, b_hh, W_dec, b_dec,
                                  out, out + (size_t)BB*TT*ODIM);
}

// round 7
// speedup vs baseline: 1.3189x; 1.3189x over previous
#include <cuda_runtime.h>
#include <cstdint>

typedef unsigned long long ull;

#define BB 512
#define TT 1024
#define IDIM 15
#define HH 64
#define ODIM 11
#define CHUNK 64
#define NCHUNK (TT/CHUNK)

// scratch (static __device__ — no allocations in kernel_launch)
__device__ __align__(16) float g_xpad[(size_t)BB*TT*16];   // x padded 15 -> 16
__device__ __align__(16) float g_hs[(size_t)BB*TT*HH];     // all hidden states

// ---- f32x2 helpers ----
__device__ __forceinline__ ull ffma2(ull a, ull b, ull c){
    ull d; asm("fma.rn.f32x2 %0, %1, %2, %3;" : "=l"(d) : "l"(a), "l"(b), "l"(c)); return d;
}
__device__ __forceinline__ ull fadd2(ull a, ull b){
    ull d; asm("add.rn.f32x2 %0, %1, %2;" : "=l"(d) : "l"(a), "l"(b)); return d;
}
__device__ __forceinline__ ull pack2(float x, float y){
    ull r; asm("mov.b64 %0, {%1, %2};" : "=l"(r) : "f"(x), "f"(y)); return r;
}
__device__ __forceinline__ float2 unpack2(ull v){
    float2 r; asm("mov.b64 {%0, %1}, %2;" : "=f"(r.x), "=f"(r.y) : "l"(v)); return r;
}

// ---- kernel 0: pad x [B,T,15] -> [B,T,16], float4 both directions via smem ----
__global__ void __launch_bounds__(256) pad_x_kernel(const float* __restrict__ x){
    __shared__ float xsm[256*IDIM];
    const int tid = threadIdx.x;
    const float4* src4 = (const float4*)(x + (size_t)blockIdx.x * (256*IDIM));
    #pragma unroll
    for (int k=0;k<4;k++){
        int idx = tid + k*256;
        if (idx < 960) ((float4*)xsm)[idx] = src4[idx];
    }
    __syncthreads();
    float4* dst4 = (float4*)(g_xpad + (size_t)blockIdx.x * (256*16));
    #pragma unroll
    for (int k=0;k<4;k++){
        int idx = tid + k*256;
        int row = idx >> 2, q = idx & 3;
        const float* rp = xsm + row*IDIM + q*4;
        float f0 = rp[0], f1 = rp[1], f2 = rp[2];
        float f3 = (q == 3) ? 0.f : rp[3];
        dst4[idx] = make_float4(f0, f1, f2, f3);
    }
}

// ---- kernel 1: fused input-proj + recurrence. warp == one batch row ----
__global__ void __launch_bounds__(128,1) rnn_kernel(
    const float* __restrict__ W_ih, const float* __restrict__ b_ih,
    const float* __restrict__ W_hh, const float* __restrict__ b_hh,
    float* __restrict__ h_out)
{
    __shared__ __align__(16) float xs[2][4][CHUNK*16];   // double-buffered x chunks
    __shared__ __align__(16) ull  h_sh[4][2][32];        // per-warp double-buffered h

    const int wid = threadIdx.x >> 5;
    const int l   = threadIdx.x & 31;
    const int b   = blockIdx.x * 4 + wid;
    const int j0 = 2*l, j1 = 2*l + 1;

    // W_hh rows j0,j1 in registers, k-paired as f32x2
    ull w0[32], w1[32];
    {
        const ull* wp = (const ull*)W_hh;
        #pragma unroll
        for (int q=0;q<32;q++){ w0[q] = wp[j0*32+q]; w1[q] = wp[j1*32+q]; }
    }
    // W_ih rows, i-paired, padded i=15 with 0
    ull wi0[8], wi1[8];
    #pragma unroll
    for (int q=0;q<8;q++){
        float a0 = W_ih[j0*IDIM + 2*q];
        float a1 = (2*q+1 < IDIM) ? W_ih[j0*IDIM + 2*q + 1] : 0.f;
        wi0[q] = pack2(a0,a1);
        float c0 = W_ih[j1*IDIM + 2*q];
        float c1 = (2*q+1 < IDIM) ? W_ih[j1*IDIM + 2*q + 1] : 0.f;
        wi1[q] = pack2(c0,c1);
    }
    const ull bias0 = pack2(b_ih[j0]+b_hh[j0], 0.f);
    const ull bias1 = pack2(b_ih[j1]+b_hh[j1], 0.f);

    h_sh[wid][1][l] = 0ULL;   // h_{-1} = 0 (t=0 reads slot 1)

    const uint32_t xs_base0 = (uint32_t)__cvta_generic_to_shared(&xs[0][wid][0]);
    const size_t xrow = (size_t)b * (TT*16);

    auto prefetch = [&](int c){
        if (c < NCHUNK){
            const float* src = g_xpad + xrow + (size_t)c*(CHUNK*16);
            uint32_t dst = xs_base0 + (uint32_t)(c & 1) * (uint32_t)sizeof(xs[0]);
            #pragma unroll
            for (int q=0;q<8;q++){
                asm volatile("cp.async.ca.shared.global [%0], [%1], 16;\n"
                    :: "r"(dst + (uint32_t)((q*32+l)*16)), "l"(src + (q*32+l)*4) : "memory");
            }
        }
        asm volatile("cp.async.commit_group;\n" ::: "memory");
    };

    prefetch(0);

    ull* hs_ptr = ((ull*)g_hs) + (size_t)b * (TT*32) + l;
    ull hlast = 0ULL;

    for (int c=0; c<NCHUNK; c++){
        prefetch(c+1);                                        // overlap next chunk
        asm volatile("cp.async.wait_group 1;\n" ::: "memory");// chunk c landed
        __syncwarp();
        const float* xbuf = &xs[c & 1][wid][0];

        #pragma unroll 2
        for (int tt=0; tt<CHUNK; tt++){
            const int rs = (tt & 1) ^ 1;   // read  h_{t-1}
            const int ws =  tt & 1;        // write h_t
            // input projection FIRST (independent of h -> fills STS->LDS shadow)
            const ulonglong2* xv = (const ulonglong2*)(xbuf + tt*16);
            ull ax0 = bias0, ax1 = bias1;
            #pragma unroll
            for (int q=0;q<4;q++){
                ulonglong2 xq = xv[q];
                ax0 = ffma2(xq.x, wi0[2*q],   ax0);
                ax1 = ffma2(xq.x, wi1[2*q],   ax1);
                ax0 = ffma2(xq.y, wi0[2*q+1], ax0);
                ax1 = ffma2(xq.y, wi1[2*q+1], ax1);
            }
            // recurrence: 64 f32x2 FMAs (== 128 fp32 FMAs) per step
            const ulonglong2* hp = (const ulonglong2*)&h_sh[wid][rs][0];
            ull aa0=0ULL, aa1=0ULL, ab0=0ULL, ab1=0ULL;
            #pragma unroll
            for (int q=0;q<16;q++){
                ulonglong2 hv = hp[q];
                aa0 = ffma2(hv.x, w0[2*q],   aa0);
                aa1 = ffma2(hv.x, w1[2*q],   aa1);
                ab0 = ffma2(hv.y, w0[2*q+1], ab0);
                ab1 = ffma2(hv.y, w1[2*q+1], ab1);
            }
            float2 s0 = unpack2(fadd2(fadd2(aa0, ab0), ax0));
            float2 s1 = unpack2(fadd2(fadd2(aa1, ab1), ax1));
            float h0v = fmaxf(s0.x + s0.y, 0.f);
            float h1v = fmaxf(s1.x + s1.y, 0.f);
            ull hpk = pack2(h0v, h1v);
            h_sh[wid][ws][l] = hpk;    // exchange for next step
            *hs_ptr = hpk;             // coalesced STG.64 of h_t for decoder kernel
            hs_ptr += 32;
            hlast = hpk;
            // converged warp: compiler-only ordering between STS and next LDS
            asm volatile("" ::: "memory");
        }
    }
    // final hidden state -> tail of d_out ( [1,B,H] )
    ((ull*)h_out)[b*32 + l] = hlast;
}

// ---- kernel 2: decoder out = relu(hs @ W_dec^T + b_dec), hs rows staged via smem ----
__global__ void __launch_bounds__(128) dec_kernel(
    const float* __restrict__ W_dec, const float* __restrict__ b_dec,
    float* __restrict__ out)
{
    __shared__ __align__(16) float wd_f[ODIM*HH];
    __shared__ float bd[ODIM];
    __shared__ __align__(16) ull  rows[4][32*33];       // padded stride: 2-way max conflict
    __shared__ __align__(16) float outsh[4][32*ODIM];

    for (int i = threadIdx.x; i < ODIM*HH; i += 128) wd_f[i] = W_dec[i];
    if (threadIdx.x < ODIM) bd[threadIdx.x] = b_dec[threadIdx.x];
    __syncthreads();

    const int wid = threadIdx.x >> 5;
    const int l   = threadIdx.x & 31;
    const int ngroups = (BB*TT)/32;   // 16384 groups of 32 rows

    for (int g = blockIdx.x*4 + wid; g < ngroups; g += gridDim.x*4){
        // coalesced load of 32 rows x 64 floats into padded smem
        const ulonglong2* src = (const ulonglong2*)(g_hs + (size_t)g * (32*64));
        #pragma unroll
        for (int q=0;q<16;q++){
            int idx = q*32 + l;            // 0..511 (16B units)
            ulonglong2 v = src[idx];
            int row = idx >> 4;
            int cu  = (idx & 15) * 2;
            rows[wid][row*33 + cu]     = v.x;
            rows[wid][row*33 + cu + 1] = v.y;
        }
        __syncwarp();
        const ull* hr  = &rows[wid][l*33];
        const ull* wd2 = (const ull*)wd_f;
        #pragma unroll
        for (int o=0;o<ODIM;o++){
            ull a0=0ULL, a1=0ULL;
            #pragma unroll
            for (int kk=0;kk<32;kk+=2){
                a0 = ffma2(hr[kk],   wd2[o*32+kk],   a0);
                a1 = ffma2(hr[kk+1], wd2[o*32+kk+1], a1);
            }
            float2 s = unpack2(fadd2(a0,a1));
            outsh[wid][l*ODIM + o] = fmaxf(s.x + s.y + bd[o], 0.f);
        }
        __syncwarp();
        // coalesced store: 32*11 = 352 floats = 88 float4
        float4* dst = (float4*)(out + (size_t)g * (32*ODIM));
        const float4* osrc = (const float4*)&outsh[wid][0];
        #pragma unroll
        for (int q=0;q<3;q++){
            int idx = q*32 + l;
            if (idx < 88) dst[idx] = osrc[idx];
        }
        __syncwarp();
    }
}

extern "C" void kernel_launch(void* const* d_in, const int* in_sizes, int n_in,
                              void* d_out, int out_size)
{
    const float* x     = (const float*)d_in[0];
    const float* W_ih  = (const float*)d_in[1];
    const float* b_ih  = (const float*)d_in[2];
    const float* W_hh  = (const float*)d_in[3];
    const float* b_hh  = (const float*)d_in[4];
    const float* W_dec = (const float*)d_in[5];
    const float* b_dec = (const float*)d_in[6];
    float* out = (float*)d_out;

    (void)in_sizes; (void)n_in; (void)out_size;

    pad_x_kernel<<<(BB*TT)/256, 256>>>(x);
    rnn_kernel<<<BB/4, 128>>>(W_ih, b_ih, W_hh, b_hh, out + (size_t)BB*TT*ODIM);
    dec_kernel<<<1024, 128>>>(W_dec, b_dec, out);
}